// round 7
// baseline (speedup 1.0000x reference)
#include <cuda_runtime.h>
#include <cuda_bf16.h>
#include <math.h>
#include <stdint.h>

#define D 64
#define NNODES 512
#define NTOT 4096
#define HDIM 192
#define EMAX 131072
#define NWARP 12
#define THREADS (NWARP * 32)
#define ROWB 144

// ---- smem layout (bytes) ----
#define OFF_WHI 0                       // [192][72] bf16 rows (144B) = 27648
#define OFF_WLO 27648
#define OFF_W2  55296                   // 192 f32 = 768
#define OFF_A   56064                   // 12 warps x (hi 4608 + lo 4608) = 110592
#define AWARP   9216
#define OFF_SS  166656                  // 12w x 32 int = 1536
#define OFF_SD  168192
#define OFF_AT  169728
#define SMEM_TOTAL 171264

__device__ float g_denom[NTOT];
__device__ float g_Pd[NTOT * HDIM];
__device__ float g_Ps[NTOT * HDIM];
__device__ int   g_is64;

__device__ __forceinline__ long long ldidx(const void* ei, int i, int is64) {
    return is64 ? ((const long long*)ei)[i] : (long long)((const int*)ei)[i];
}
__device__ __forceinline__ void ldsm4(uint32_t* r, uint32_t a) {
    asm volatile("ldmatrix.sync.aligned.m8n8.x4.shared.b16 {%0,%1,%2,%3}, [%4];"
                 : "=r"(r[0]), "=r"(r[1]), "=r"(r[2]), "=r"(r[3]) : "r"(a));
}
__device__ __forceinline__ void mma_bf16(float* c, const uint32_t* a, const uint32_t* b) {
    asm volatile("mma.sync.aligned.m16n8k16.row.col.f32.bf16.bf16.f32 "
                 "{%0,%1,%2,%3}, {%4,%5,%6,%7}, {%8,%9}, {%0,%1,%2,%3};"
                 : "+f"(c[0]), "+f"(c[1]), "+f"(c[2]), "+f"(c[3])
                 : "r"(a[0]), "r"(a[1]), "r"(a[2]), "r"(a[3]), "r"(b[0]), "r"(b[1]));
}
__device__ __forceinline__ void red4(float* p, float a, float b, float c, float d) {
    asm volatile("red.global.add.v4.f32 [%0], {%1,%2,%3,%4};"
                 :: "l"(p), "f"(a), "f"(b), "f"(c), "f"(d) : "memory");
}
__device__ __forceinline__ uint2 pack_hi_lo(float4 v, uint2* lo) {
    __nv_bfloat16 h0 = __float2bfloat16(v.x), h1 = __float2bfloat16(v.y);
    __nv_bfloat16 h2 = __float2bfloat16(v.z), h3 = __float2bfloat16(v.w);
    __nv_bfloat16 l0 = __float2bfloat16(v.x - __bfloat162float(h0));
    __nv_bfloat16 l1 = __float2bfloat16(v.y - __bfloat162float(h1));
    __nv_bfloat16 l2 = __float2bfloat16(v.z - __bfloat162float(h2));
    __nv_bfloat16 l3 = __float2bfloat16(v.w - __bfloat162float(h3));
    uint2 hi, lv;
    hi.x = (uint32_t)__bfloat16_as_ushort(h0) | ((uint32_t)__bfloat16_as_ushort(h1) << 16);
    hi.y = (uint32_t)__bfloat16_as_ushort(h2) | ((uint32_t)__bfloat16_as_ushort(h3) << 16);
    lv.x = (uint32_t)__bfloat16_as_ushort(l0) | ((uint32_t)__bfloat16_as_ushort(l1) << 16);
    lv.y = (uint32_t)__bfloat16_as_ushort(l2) | ((uint32_t)__bfloat16_as_ushort(l3) << 16);
    *lo = lv;
    return hi;
}
__device__ __forceinline__ float gelu_x(float x) {
    return 0.5f * x * (1.0f + erff(x * 0.70710678118654752f));
}

// zero + int64/int32 detection (block 0)
__global__ void zero_kernel(float* __restrict__ out, const void* __restrict__ ei) {
    int i = blockIdx.x * blockDim.x + threadIdx.x;
    if (i < NTOT * D) out[i] = 0.0f;
    if (i < NTOT)     g_denom[i] = 0.0f;
    if (blockIdx.x == 0) {
        const long long* p = (const long long*)ei;
        long long v = p[threadIdx.x];
        int ok = (v >= 0 && v < NTOT);
        int all = __syncthreads_and(ok);
        if (threadIdx.x == 0) g_is64 = all;
    }
}

// P[n][o] = sum_k nf[n][k] * W1[o][64*half + k]  (fp32 exact, plain layout)
__global__ __launch_bounds__(256, 2) void precompute_kernel(
    const float* __restrict__ nf, const float* __restrict__ W1)
{
    extern __shared__ float psm[];
    float* Ws = psm;                // [64][192]: Ws[k*192+o]
    float* Ns = psm + 64 * HDIM;    // [64][64]

    int half = blockIdx.x & 1;
    int tile = blockIdx.x >> 1;
    int tid = threadIdx.x, lane = tid & 31, warp = tid >> 5;
    float* P = half ? g_Ps : g_Pd;

    for (int i = tid; i < HDIM * 64; i += 256) {
        int o = i >> 6, k = i & 63;
        Ws[k * HDIM + o] = W1[o * HDIM + 64 * half + k];
    }
    for (int i = tid; i < 64 * 64 / 4; i += 256)
        ((float4*)Ns)[i] = ((const float4*)(nf + tile * 64 * D))[i];
    __syncthreads();

    float acc[8][6];
    #pragma unroll
    for (int e = 0; e < 8; ++e)
        #pragma unroll
        for (int j = 0; j < 6; ++j) acc[e][j] = 0.0f;

    const float* hb = Ns + (warp * 8) * 64;
    #pragma unroll 4
    for (int k = 0; k < 64; ++k) {
        const float* w = Ws + k * HDIM + lane;
        float wv[6];
        #pragma unroll
        for (int j = 0; j < 6; ++j) wv[j] = w[32 * j];
        #pragma unroll
        for (int e = 0; e < 8; ++e) {
            float hv = hb[e * 64 + k];
            #pragma unroll
            for (int j = 0; j < 6; ++j) acc[e][j] = fmaf(hv, wv[j], acc[e][j]);
        }
    }
    int nbase = tile * 64 + warp * 8;
    #pragma unroll
    for (int e = 0; e < 8; ++e)
        #pragma unroll
        for (int j = 0; j < 6; ++j)
            P[(nbase + e) * HDIM + lane + 32 * j] = acc[e][j];
}

// Warp-autonomous: 32-edge warp tiles as TWO m=16 MMA A-sets sharing each W
// B-fragment (ldsm4 loads B for two 8-col groups at once). Acc init with
// Pd[dst]+Ps[src]; gelu*W2 epilogue; exp/mask; denom atomic; red.v4 output.
__global__ __launch_bounds__(THREADS, 1) void score_kernel(
    const float* __restrict__ adj, const float* __restrict__ W1,
    const float* __restrict__ W2, const void* __restrict__ ei,
    float* __restrict__ out, int E, int nwt)
{
    extern __shared__ __align__(16) char sm[];
    uint32_t smb = (uint32_t)__cvta_generic_to_shared(sm);
    float* W2s = (float*)(sm + OFF_W2);

    int tid = threadIdx.x, lane = tid & 31, wid = tid >> 5;
    int is64 = g_is64;

    // Stage W1c (cols 128..191) split hi/lo (rows = output o, K-major, 144B rows)
    for (int i = tid; i < HDIM * 16; i += THREADS) {
        int o = i >> 4, r = i & 15;
        float4 v = *(const float4*)(W1 + o * HDIM + 128 + r * 4);
        uint2 lo, hi = pack_hi_lo(v, &lo);
        *(uint2*)(sm + OFF_WHI + o * ROWB + r * 8) = hi;
        *(uint2*)(sm + OFF_WLO + o * ROWB + r * 8) = lo;
    }
    for (int i = tid; i < HDIM; i += THREADS) W2s[i] = W2[i];
    __syncthreads();

    char* Ahi = sm + OFF_A + wid * AWARP;
    char* Alo = Ahi + 4608;
    uint32_t ahi_u = smb + OFF_A + wid * AWARP;
    uint32_t whi_u = smb + OFF_WHI;
    int*   sSw = (int*)(sm + OFF_SS) + wid * 32;
    int*   sDw = (int*)(sm + OFF_SD) + wid * 32;
    float* ATw = (float*)(sm + OFF_AT) + wid * 32;

    int gw = blockIdx.x * NWARP + wid;
    for (int wt = gw; wt < nwt; wt += gridDim.x * NWARP) {
        int tbase = wt * 32;
        // ---- indices: one edge per lane ----
        int ge = tbase + lane;
        long long sL = 0, dL = 0;
        if (ge < E) {
            sL = ldidx(ei, ge, is64);
            dL = ldidx(ei, E + ge, is64);
        }
        sSw[lane] = (int)sL; sDw[lane] = (int)dL;
        // ---- gather + split own adj row (stagger j to spread STS banks) ----
        {
            const float4* rowp =
                (const float4*)(adj + (sL * NNODES + ((int)dL & (NNODES - 1))) * D);
            #pragma unroll
            for (int j = 0; j < 16; ++j) {
                int jl = (j + ((lane >> 3) << 2)) & 15;
                float4 v = (ge < E) ? rowp[jl] : make_float4(0.f, 0.f, 0.f, 0.f);
                uint2 lo, hi = pack_hi_lo(v, &lo);
                *(uint2*)(Ahi + lane * ROWB + jl * 8) = hi;
                *(uint2*)(Alo + lane * ROWB + jl * 8) = lo;
            }
        }
        __syncwarp();

        // thread's 4 edges (2 per set): rows r0, r0+8 within each m=16 set
        int r0 = lane >> 2;
        const float* pd00 = g_Pd + sDw[r0] * HDIM;
        const float* ps00 = g_Ps + sSw[r0] * HDIM;
        const float* pd01 = g_Pd + sDw[r0 + 8] * HDIM;
        const float* ps01 = g_Ps + sSw[r0 + 8] * HDIM;
        const float* pd10 = g_Pd + sDw[r0 + 16] * HDIM;
        const float* ps10 = g_Ps + sSw[r0 + 16] * HDIM;
        const float* pd11 = g_Pd + sDw[r0 + 24] * HDIM;
        const float* ps11 = g_Ps + sSw[r0 + 24] * HDIM;

        float z00 = 0.f, z01 = 0.f, z10 = 0.f, z11 = 0.f;
        #pragma unroll
        for (int nc = 0; nc < 3; ++nc) {
            int cb = nc * 64;
            float acc0[8][4], acc1[8][4];
            #pragma unroll
            for (int f = 0; f < 8; ++f) {
                int c0 = cb + f * 8 + 2 * (lane & 3);
                float2 a, b;
                a = *(const float2*)(pd00 + c0); b = *(const float2*)(ps00 + c0);
                acc0[f][0] = a.x + b.x; acc0[f][1] = a.y + b.y;
                a = *(const float2*)(pd01 + c0); b = *(const float2*)(ps01 + c0);
                acc0[f][2] = a.x + b.x; acc0[f][3] = a.y + b.y;
                a = *(const float2*)(pd10 + c0); b = *(const float2*)(ps10 + c0);
                acc1[f][0] = a.x + b.x; acc1[f][1] = a.y + b.y;
                a = *(const float2*)(pd11 + c0); b = *(const float2*)(ps11 + c0);
                acc1[f][2] = a.x + b.x; acc1[f][3] = a.y + b.y;
            }
            #pragma unroll
            for (int kk = 0; kk < 4; ++kk) {
                // A fragments for both 16-edge sets (hi & lo)
                uint32_t a0 = ahi_u + (uint32_t)((lane & 15) * ROWB + kk * 32 + (lane >> 4) * 16);
                uint32_t a1 = a0 + 16 * ROWB;
                uint32_t ah0[4], al0[4], ah1[4], al1[4];
                ldsm4(ah0, a0); ldsm4(al0, a0 + 4608);
                ldsm4(ah1, a1); ldsm4(al1, a1 + 4608);
                #pragma unroll
                for (int fp = 0; fp < 4; ++fp) {
                    // B frags for col groups f=2fp, 2fp+1 in ONE ldsm4
                    uint32_t wa = whi_u + (uint32_t)((cb + fp * 16 + (lane & 7) + ((lane >> 4) << 3)) * ROWB
                                                     + kk * 32 + ((lane >> 3) & 1) * 16);
                    uint32_t bh[4], bl[4];
                    ldsm4(bh, wa);
                    ldsm4(bl, wa + 27648);
                    mma_bf16(acc0[2*fp],   ah0, bh);     mma_bf16(acc0[2*fp],   ah0, bl);
                    mma_bf16(acc0[2*fp],   al0, bh);
                    mma_bf16(acc0[2*fp+1], ah0, bh + 2); mma_bf16(acc0[2*fp+1], ah0, bl + 2);
                    mma_bf16(acc0[2*fp+1], al0, bh + 2);
                    mma_bf16(acc1[2*fp],   ah1, bh);     mma_bf16(acc1[2*fp],   ah1, bl);
                    mma_bf16(acc1[2*fp],   al1, bh);
                    mma_bf16(acc1[2*fp+1], ah1, bh + 2); mma_bf16(acc1[2*fp+1], ah1, bl + 2);
                    mma_bf16(acc1[2*fp+1], al1, bh + 2);
                }
            }
            #pragma unroll
            for (int f = 0; f < 8; ++f) {
                int c0 = cb + f * 8 + 2 * (lane & 3);
                float2 w2v = *(const float2*)(W2s + c0);
                z00 = fmaf(gelu_x(acc0[f][0]), w2v.x, z00);
                z00 = fmaf(gelu_x(acc0[f][1]), w2v.y, z00);
                z01 = fmaf(gelu_x(acc0[f][2]), w2v.x, z01);
                z01 = fmaf(gelu_x(acc0[f][3]), w2v.y, z01);
                z10 = fmaf(gelu_x(acc1[f][0]), w2v.x, z10);
                z10 = fmaf(gelu_x(acc1[f][1]), w2v.y, z10);
                z11 = fmaf(gelu_x(acc1[f][2]), w2v.x, z11);
                z11 = fmaf(gelu_x(acc1[f][3]), w2v.y, z11);
            }
        }

        // quad reduce (lanes covering the 8 columns of each edge row)
        z00 += __shfl_xor_sync(0xffffffffu, z00, 1);
        z00 += __shfl_xor_sync(0xffffffffu, z00, 2);
        z01 += __shfl_xor_sync(0xffffffffu, z01, 1);
        z01 += __shfl_xor_sync(0xffffffffu, z01, 2);
        z10 += __shfl_xor_sync(0xffffffffu, z10, 1);
        z10 += __shfl_xor_sync(0xffffffffu, z10, 2);
        z11 += __shfl_xor_sync(0xffffffffu, z11, 1);
        z11 += __shfl_xor_sync(0xffffffffu, z11, 2);

        if ((lane & 3) == 0) {
            float zv[4] = {z00, z01, z10, z11};
            #pragma unroll
            for (int q = 0; q < 4; ++q) {
                int e = r0 + q * 8;
                int s = sSw[e], d = sDw[e];
                int df = s > d ? s - d : d - s;
                float attn = (tbase + e < E && df > 1) ? expf(zv[q]) : 0.0f;
                ATw[e] = attn;
                if (attn != 0.0f) atomicAdd(&g_denom[d], attn);
            }
        }
        __syncwarp();

        // weighted accumulate: 2 edges per pass, 4 cols/lane, red.v4
        #pragma unroll
        for (int ep = 0; ep < 16; ++ep) {
            int e = 2 * ep + (lane >> 4);
            float a = ATw[e];
            if (a != 0.0f) {
                int c4 = lane & 15;
                uint2 h = *(const uint2*)(Ahi + e * ROWB + c4 * 8);
                uint2 l = *(const uint2*)(Alo + e * ROWB + c4 * 8);
                float f0 = __uint_as_float((h.x & 0xffffu) << 16) + __uint_as_float((l.x & 0xffffu) << 16);
                float f1 = __uint_as_float(h.x & 0xffff0000u)     + __uint_as_float(l.x & 0xffff0000u);
                float f2 = __uint_as_float((h.y & 0xffffu) << 16) + __uint_as_float((l.y & 0xffffu) << 16);
                float f3 = __uint_as_float(h.y & 0xffff0000u)     + __uint_as_float(l.y & 0xffff0000u);
                red4(out + sDw[e] * D + c4 * 4, f0 * a, f1 * a, f2 * a, f3 * a);
            }
        }
        __syncwarp();
    }
}

__global__ void finalize_kernel(float* __restrict__ out) {
    int i = blockIdx.x * blockDim.x + threadIdx.x;
    if (i < NTOT * D) {
        float dn = g_denom[i >> 6];
        out[i] = out[i] / (dn == 0.0f ? 1.0f : dn);
    }
}

extern "C" void kernel_launch(void* const* d_in, const int* in_sizes, int n_in,
                              void* d_out, int out_size) {
    const float* nf  = (const float*)d_in[0];
    const float* adj = (const float*)d_in[1];
    const float* W1  = (const float*)d_in[2];
    const float* W2  = (const float*)d_in[3];
    const void*  ei  = d_in[4];
    int E = in_sizes[4] / 2;
    if (E > EMAX) E = EMAX;

    const int pre_smem = (64 * HDIM + 64 * 64) * sizeof(float);
    cudaFuncSetAttribute(precompute_kernel, cudaFuncAttributeMaxDynamicSharedMemorySize, pre_smem);
    cudaFuncSetAttribute(score_kernel, cudaFuncAttributeMaxDynamicSharedMemorySize, SMEM_TOTAL);

    zero_kernel<<<(NTOT * D + 255) / 256, 256>>>((float*)d_out, ei);
    precompute_kernel<<<(NTOT / 64) * 2, 256, pre_smem>>>(nf, W1);

    int nwt = (E + 31) / 32;
    int grid = (nwt + NWARP - 1) / NWARP;
    if (grid > 148) grid = 148;
    score_kernel<<<grid, THREADS, SMEM_TOTAL>>>(adj, W1, W2, ei, (float*)d_out, E, nwt);

    finalize_kernel<<<(NTOT * D + 255) / 256, 256>>>((float*)d_out);
}

// round 8
// speedup vs baseline: 1.4726x; 1.4726x over previous
#include <cuda_runtime.h>
#include <cuda_fp16.h>
#include <math.h>
#include <stdint.h>

#define D 64
#define NNODES 512
#define NTOT 4096
#define HDIM 192
#define EMAX 131072
#define NWARP 16
#define THREADS (NWARP * 32)
#define ROWB 144
#define F32RB 272

// ---- smem layout (bytes) ----
#define OFF_W   0                        // [192][72] fp16 rows (144B) = 27648
#define OFF_W2  27648                    // 192 f32 = 768
#define OFF_A   28416                    // 16 warps x 6912
#define AWARP   6912                     //  fp16 rows [16][144]=2304 ; f32 rows [16][272]=4352 @+2304
#define OFF_SS  139008                   // 16w x 16 int = 1024
#define OFF_SD  140032
#define OFF_AT  141056
#define SMEM_TOTAL 142080

__device__ float g_denom[NTOT];
__device__ float g_Pd[NTOT * HDIM];
__device__ float g_Ps[NTOT * HDIM];
__device__ int   g_is64;

__device__ __forceinline__ long long ldidx(const void* ei, int i, int is64) {
    return is64 ? ((const long long*)ei)[i] : (long long)((const int*)ei)[i];
}
__device__ __forceinline__ void ldsm4(uint32_t* r, uint32_t a) {
    asm volatile("ldmatrix.sync.aligned.m8n8.x4.shared.b16 {%0,%1,%2,%3}, [%4];"
                 : "=r"(r[0]), "=r"(r[1]), "=r"(r[2]), "=r"(r[3]) : "r"(a));
}
__device__ __forceinline__ void mma_fp16(float* c, const uint32_t* a, const uint32_t* b) {
    asm volatile("mma.sync.aligned.m16n8k16.row.col.f32.f16.f16.f32 "
                 "{%0,%1,%2,%3}, {%4,%5,%6,%7}, {%8,%9}, {%0,%1,%2,%3};"
                 : "+f"(c[0]), "+f"(c[1]), "+f"(c[2]), "+f"(c[3])
                 : "r"(a[0]), "r"(a[1]), "r"(a[2]), "r"(a[3]), "r"(b[0]), "r"(b[1]));
}
__device__ __forceinline__ void red4(float* p, float a, float b, float c, float d) {
    asm volatile("red.global.add.v4.f32 [%0], {%1,%2,%3,%4};"
                 :: "l"(p), "f"(a), "f"(b), "f"(c), "f"(d) : "memory");
}
__device__ __forceinline__ uint2 pack_h4(float4 v) {
    __half2 p0 = __floats2half2_rn(v.x, v.y);
    __half2 p1 = __floats2half2_rn(v.z, v.w);
    uint2 u;
    u.x = *reinterpret_cast<uint32_t*>(&p0);
    u.y = *reinterpret_cast<uint32_t*>(&p1);
    return u;
}
__device__ __forceinline__ float gelu_x(float x) {
    return 0.5f * x * (1.0f + erff(x * 0.70710678118654752f));
}

// zero + int64/int32 detection (block 0)
__global__ void zero_kernel(float* __restrict__ out, const void* __restrict__ ei) {
    int i = blockIdx.x * blockDim.x + threadIdx.x;
    if (i < NTOT * D) out[i] = 0.0f;
    if (i < NTOT)     g_denom[i] = 0.0f;
    if (blockIdx.x == 0) {
        const long long* p = (const long long*)ei;
        long long v = p[threadIdx.x];
        int ok = (v >= 0 && v < NTOT);
        int all = __syncthreads_and(ok);
        if (threadIdx.x == 0) g_is64 = all;
    }
}

// P[n][o] = sum_k nf[n][k] * W1[o][64*half + k]  (fp32 exact)
__global__ __launch_bounds__(256, 2) void precompute_kernel(
    const float* __restrict__ nf, const float* __restrict__ W1)
{
    extern __shared__ float psm[];
    float* Ws = psm;                // [64][192]: Ws[k*192+o]
    float* Ns = psm + 64 * HDIM;    // [64][64]

    int half = blockIdx.x & 1;
    int tile = blockIdx.x >> 1;
    int tid = threadIdx.x, lane = tid & 31, warp = tid >> 5;
    float* P = half ? g_Ps : g_Pd;

    for (int i = tid; i < HDIM * 64; i += 256) {
        int o = i >> 6, k = i & 63;
        Ws[k * HDIM + o] = W1[o * HDIM + 64 * half + k];
    }
    for (int i = tid; i < 64 * 64 / 4; i += 256)
        ((float4*)Ns)[i] = ((const float4*)(nf + tile * 64 * D))[i];
    __syncthreads();

    float acc[8][6];
    #pragma unroll
    for (int e = 0; e < 8; ++e)
        #pragma unroll
        for (int j = 0; j < 6; ++j) acc[e][j] = 0.0f;

    const float* hb = Ns + (warp * 8) * 64;
    #pragma unroll 4
    for (int k = 0; k < 64; ++k) {
        const float* w = Ws + k * HDIM + lane;
        float wv[6];
        #pragma unroll
        for (int j = 0; j < 6; ++j) wv[j] = w[32 * j];
        #pragma unroll
        for (int e = 0; e < 8; ++e) {
            float hv = hb[e * 64 + k];
            #pragma unroll
            for (int j = 0; j < 6; ++j) acc[e][j] = fmaf(hv, wv[j], acc[e][j]);
        }
    }
    int nbase = tile * 64 + warp * 8;
    #pragma unroll
    for (int e = 0; e < 8; ++e)
        #pragma unroll
        for (int j = 0; j < 6; ++j)
            P[(nbase + e) * HDIM + lane + 32 * j] = acc[e][j];
}

// Warp-autonomous fused kernel: 16-edge warp tiles, SINGLE fp16 MMA per
// (kk,f) pair (no split). Acc initialized with Pd[dst]+Ps[src]. Exact fp32
// edge rows kept in smem for the output accumulate.
__global__ __launch_bounds__(THREADS, 1) void score_kernel(
    const float* __restrict__ adj, const float* __restrict__ W1,
    const float* __restrict__ W2, const void* __restrict__ ei,
    float* __restrict__ out, int E, int nwt)
{
    extern __shared__ __align__(16) char sm[];
    uint32_t smb = (uint32_t)__cvta_generic_to_shared(sm);
    float* W2s = (float*)(sm + OFF_W2);

    int tid = threadIdx.x, lane = tid & 31, wid = tid >> 5;
    int is64 = g_is64;

    // Stage W1c (cols 128..191) as fp16, rows = output o, K-major, 144B rows
    for (int i = tid; i < HDIM * 16; i += THREADS) {
        int o = i >> 4, r = i & 15;
        float4 v = *(const float4*)(W1 + o * HDIM + 128 + r * 4);
        *(uint2*)(sm + OFF_W + o * ROWB + r * 8) = pack_h4(v);
    }
    for (int i = tid; i < HDIM; i += THREADS) W2s[i] = W2[i];
    __syncthreads();

    char* Ah  = sm + OFF_A + wid * AWARP;       // fp16 rows [16][144]
    char* F32 = Ah + 2304;                      // fp32 rows [16][272]
    uint32_t ah_u = smb + OFF_A + wid * AWARP;
    uint32_t w_u  = smb + OFF_W;
    int*   sSw = (int*)(sm + OFF_SS) + wid * 16;
    int*   sDw = (int*)(sm + OFF_SD) + wid * 16;
    float* ATw = (float*)(sm + OFF_AT) + wid * 16;

    int gw = blockIdx.x * NWARP + wid;
    for (int wt = gw; wt < nwt; wt += gridDim.x * NWARP) {
        int tbase = wt * 16;
        // ---- stage indices ----
        if (lane < 16) {
            int ge = tbase + lane;
            int s = 0, d = 0;
            if (ge < E) {
                s = (int)ldidx(ei, ge, is64);
                d = (int)ldidx(ei, E + ge, is64);
            }
            sSw[lane] = s; sDw[lane] = d;
        }
        __syncwarp();
        // ---- gather adj rows: fp16 copy for MMA + fp32 copy for output ----
        {
            int r = lane >> 1, h = lane & 1;
            int ge = tbase + r;
            int s = sSw[r], d = sDw[r];
            const float4* rowp =
                (const float4*)(adj + ((long long)s * NNODES + (d & (NNODES - 1))) * D);
            #pragma unroll
            for (int j = 0; j < 8; ++j) {
                float4 v = (ge < E) ? rowp[h * 8 + j]
                                    : make_float4(0.f, 0.f, 0.f, 0.f);
                *(uint2*)(Ah + r * ROWB + (h * 8 + j) * 8) = pack_h4(v);
                *(float4*)(F32 + r * F32RB + (h * 8 + j) * 16) = v;
            }
        }
        __syncwarp();

        int r0 = lane >> 2, r1 = r0 + 8;
        int s0 = sSw[r0], d0 = sDw[r0], s1 = sSw[r1], d1 = sDw[r1];
        const float* pd0 = g_Pd + d0 * HDIM;
        const float* ps0 = g_Ps + s0 * HDIM;
        const float* pd1 = g_Pd + d1 * HDIM;
        const float* ps1 = g_Ps + s1 * HDIM;

        float z0 = 0.0f, z1 = 0.0f;
        #pragma unroll
        for (int nc = 0; nc < 3; ++nc) {
            float acc[8][4];
            int cb = nc * 64;
            #pragma unroll
            for (int f = 0; f < 8; ++f) {
                int c0 = cb + f * 8 + 2 * (lane & 3);
                float2 a0 = *(const float2*)(pd0 + c0);
                float2 b0 = *(const float2*)(ps0 + c0);
                float2 a1 = *(const float2*)(pd1 + c0);
                float2 b1 = *(const float2*)(ps1 + c0);
                acc[f][0] = a0.x + b0.x; acc[f][1] = a0.y + b0.y;
                acc[f][2] = a1.x + b1.x; acc[f][3] = a1.y + b1.y;
            }
            #pragma unroll
            for (int kk = 0; kk < 4; ++kk) {
                uint32_t aoff = (uint32_t)((lane & 15) * ROWB + kk * 32 + (lane >> 4) * 16);
                uint32_t ah[4];
                ldsm4(ah, ah_u + aoff);
                #pragma unroll
                for (int fp = 0; fp < 4; ++fp) {
                    // B frags for col groups f=2fp, 2fp+1 in one ldsm4
                    uint32_t wa = w_u + (uint32_t)((cb + fp * 16 + (lane & 7) + ((lane >> 4) << 3)) * ROWB
                                                   + kk * 32 + ((lane >> 3) & 1) * 16);
                    uint32_t bh[4];
                    ldsm4(bh, wa);
                    mma_fp16(acc[2 * fp],     ah, bh);
                    mma_fp16(acc[2 * fp + 1], ah, bh + 2);
                }
            }
            // epilogue partial: z += gelu(y) * W2
            #pragma unroll
            for (int f = 0; f < 8; ++f) {
                int c0 = cb + f * 8 + 2 * (lane & 3);
                float2 w2v = *(const float2*)(W2s + c0);
                z0 = fmaf(gelu_x(acc[f][0]), w2v.x, z0);
                z0 = fmaf(gelu_x(acc[f][1]), w2v.y, z0);
                z1 = fmaf(gelu_x(acc[f][2]), w2v.x, z1);
                z1 = fmaf(gelu_x(acc[f][3]), w2v.y, z1);
            }
        }
        // quad reduce (lanes sharing the same rows)
        z0 += __shfl_xor_sync(0xffffffffu, z0, 1);
        z0 += __shfl_xor_sync(0xffffffffu, z0, 2);
        z1 += __shfl_xor_sync(0xffffffffu, z1, 1);
        z1 += __shfl_xor_sync(0xffffffffu, z1, 2);

        if ((lane & 3) == 0) {
            int df0 = (s0 > d0 ? s0 - d0 : d0 - s0);
            int df1 = (s1 > d1 ? s1 - d1 : d1 - s1);
            float at0 = (tbase + r0 < E && df0 > 1) ? expf(z0) : 0.0f;
            float at1 = (tbase + r1 < E && df1 > 1) ? expf(z1) : 0.0f;
            ATw[r0] = at0; ATw[r1] = at1;
            if (at0 != 0.0f) atomicAdd(&g_denom[d0], at0);
            if (at1 != 0.0f) atomicAdd(&g_denom[d1], at1);
        }
        __syncwarp();

        // weighted accumulate from the exact fp32 rows: 2 edges/pass, red.v4
        #pragma unroll
        for (int ep = 0; ep < 8; ++ep) {
            int e = 2 * ep + (lane >> 4);
            float a = ATw[e];
            if (a != 0.0f) {
                int c4 = lane & 15;
                float4 v = *(const float4*)(F32 + e * F32RB + c4 * 16);
                red4(out + sDw[e] * D + c4 * 4, v.x * a, v.y * a, v.z * a, v.w * a);
            }
        }
        __syncwarp();
    }
}

__global__ void finalize_kernel(float* __restrict__ out) {
    int i = blockIdx.x * blockDim.x + threadIdx.x;
    if (i < NTOT * D) {
        float dn = g_denom[i >> 6];
        out[i] = out[i] / (dn == 0.0f ? 1.0f : dn);
    }
}

extern "C" void kernel_launch(void* const* d_in, const int* in_sizes, int n_in,
                              void* d_out, int out_size) {
    const float* nf  = (const float*)d_in[0];
    const float* adj = (const float*)d_in[1];
    const float* W1  = (const float*)d_in[2];
    const float* W2  = (const float*)d_in[3];
    const void*  ei  = d_in[4];
    int E = in_sizes[4] / 2;
    if (E > EMAX) E = EMAX;

    const int pre_smem = (64 * HDIM + 64 * 64) * sizeof(float);
    cudaFuncSetAttribute(precompute_kernel, cudaFuncAttributeMaxDynamicSharedMemorySize, pre_smem);
    cudaFuncSetAttribute(score_kernel, cudaFuncAttributeMaxDynamicSharedMemorySize, SMEM_TOTAL);

    zero_kernel<<<(NTOT * D + 255) / 256, 256>>>((float*)d_out, ei);
    precompute_kernel<<<(NTOT / 64) * 2, 256, pre_smem>>>(nf, W1);

    int nwt = (E + 15) / 16;
    int grid = 148;
    score_kernel<<<grid, THREADS, SMEM_TOTAL>>>(adj, W1, W2, ei, (float*)d_out, E, nwt);

    finalize_kernel<<<(NTOT * D + 255) / 256, 256>>>((float*)d_out);
}

// round 9
// speedup vs baseline: 1.5497x; 1.0523x over previous
#include <cuda_runtime.h>
#include <cuda_fp16.h>
#include <math.h>
#include <stdint.h>

#define D 64
#define NNODES 512
#define NTOT 4096
#define HDIM 192
#define EMAX 131072
#define NWARP 16
#define THREADS (NWARP * 32)
#define ROWB 144
#define F32RB 272

// ---- smem layout (bytes) ----
#define OFF_W   0                        // [192][72] fp16 rows (144B) = 27648
#define OFF_W2  27648                    // 192 f32 = 768
#define OFF_A   28416                    // 16 warps x 6912
#define AWARP   6912                     //  fp16 rows [16][144]=2304 ; f32 rows [16][272]=4352 @+2304
#define OFF_SS  139008                   // 16w x 16 int = 1024
#define OFF_SD  140032
#define OFF_AT  141056
#define SMEM_TOTAL 142080

__device__ float  g_denom[NTOT];
__device__ __half g_PdH[NTOT * HDIM];   // fp16 P: nf @ W1[:,0:64]^T
__device__ __half g_PsH[NTOT * HDIM];   // fp16 P: nf @ W1[:,64:128]^T
__device__ int    g_is64;

__device__ __forceinline__ long long ldidx(const void* ei, int i, int is64) {
    return is64 ? ((const long long*)ei)[i] : (long long)((const int*)ei)[i];
}
__device__ __forceinline__ void ldsm4(uint32_t* r, uint32_t a) {
    asm volatile("ldmatrix.sync.aligned.m8n8.x4.shared.b16 {%0,%1,%2,%3}, [%4];"
                 : "=r"(r[0]), "=r"(r[1]), "=r"(r[2]), "=r"(r[3]) : "r"(a));
}
__device__ __forceinline__ void mma_fp16(float* c, const uint32_t* a, const uint32_t* b) {
    asm volatile("mma.sync.aligned.m16n8k16.row.col.f32.f16.f16.f32 "
                 "{%0,%1,%2,%3}, {%4,%5,%6,%7}, {%8,%9}, {%0,%1,%2,%3};"
                 : "+f"(c[0]), "+f"(c[1]), "+f"(c[2]), "+f"(c[3])
                 : "r"(a[0]), "r"(a[1]), "r"(a[2]), "r"(a[3]), "r"(b[0]), "r"(b[1]));
}
__device__ __forceinline__ void red4(float* p, float a, float b, float c, float d) {
    asm volatile("red.global.add.v4.f32 [%0], {%1,%2,%3,%4};"
                 :: "l"(p), "f"(a), "f"(b), "f"(c), "f"(d) : "memory");
}
__device__ __forceinline__ uint2 pack_h4(float4 v) {
    __half2 p0 = __floats2half2_rn(v.x, v.y);
    __half2 p1 = __floats2half2_rn(v.z, v.w);
    uint2 u;
    u.x = *reinterpret_cast<uint32_t*>(&p0);
    u.y = *reinterpret_cast<uint32_t*>(&p1);
    return u;
}
__device__ __forceinline__ float gelu_x(float x) {
    return 0.5f * x * (1.0f + erff(x * 0.70710678118654752f));
}

// Fused: zero out/denom (all 128 blocks), int-width detect (block 0),
// P[n][o] = sum_k nf[n][k]*W1[o][64*half+k] (fp32 compute, fp16 store).
__global__ __launch_bounds__(256, 2) void precompute_kernel(
    const float* __restrict__ nf, const float* __restrict__ W1,
    const void* __restrict__ ei, float* __restrict__ out)
{
    extern __shared__ float psm[];
    float* Ws = psm;                // [64][192]: Ws[k*192+o]
    float* Ns = psm + 64 * HDIM;    // [64][64]

    int half = blockIdx.x & 1;
    int tile = blockIdx.x >> 1;
    int tid = threadIdx.x, lane = tid & 31, warp = tid >> 5;
    __half* P = half ? g_PsH : g_PdH;

    // zero out + denom (128 blocks cover NTOT*D floats; 512 float4 per block)
    {
        float4 z4 = make_float4(0.f, 0.f, 0.f, 0.f);
        ((float4*)out)[blockIdx.x * 512 + tid]       = z4;
        ((float4*)out)[blockIdx.x * 512 + 256 + tid] = z4;
        if (tid < 32) g_denom[blockIdx.x * 32 + tid] = 0.0f;
    }
    // int64 vs int32 detect (block 0; range-probe 256 int64 words)
    if (blockIdx.x == 0) {
        const long long* p = (const long long*)ei;
        long long v = p[tid];
        int ok = (v >= 0 && v < NTOT);
        int all = __syncthreads_and(ok);
        if (tid == 0) g_is64 = all;
    }

    for (int i = tid; i < HDIM * 64; i += 256) {
        int o = i >> 6, k = i & 63;
        Ws[k * HDIM + o] = W1[o * HDIM + 64 * half + k];
    }
    for (int i = tid; i < 64 * 64 / 4; i += 256)
        ((float4*)Ns)[i] = ((const float4*)(nf + tile * 64 * D))[i];
    __syncthreads();

    float acc[8][6];
    #pragma unroll
    for (int e = 0; e < 8; ++e)
        #pragma unroll
        for (int j = 0; j < 6; ++j) acc[e][j] = 0.0f;

    const float* hb = Ns + (warp * 8) * 64;
    #pragma unroll 4
    for (int k = 0; k < 64; ++k) {
        const float* w = Ws + k * HDIM + lane;
        float wv[6];
        #pragma unroll
        for (int j = 0; j < 6; ++j) wv[j] = w[32 * j];
        #pragma unroll
        for (int e = 0; e < 8; ++e) {
            float hv = hb[e * 64 + k];
            #pragma unroll
            for (int j = 0; j < 6; ++j) acc[e][j] = fmaf(hv, wv[j], acc[e][j]);
        }
    }
    int nbase = tile * 64 + warp * 8;
    #pragma unroll
    for (int e = 0; e < 8; ++e)
        #pragma unroll
        for (int j = 0; j < 6; ++j)
            P[(nbase + e) * HDIM + lane + 32 * j] = __float2half(acc[e][j]);
}

// Warp-autonomous fused kernel: 16-edge warp tiles, single fp16 MMA, acc
// zero-init (P folded into the gelu epilogue to decouple L2 latency from
// the MMA chain). Exact fp32 edge rows kept in smem for output accumulate.
__global__ __launch_bounds__(THREADS, 1) void score_kernel(
    const float* __restrict__ adj, const float* __restrict__ W1,
    const float* __restrict__ W2, const void* __restrict__ ei,
    float* __restrict__ out, int E, int nwt)
{
    extern __shared__ __align__(16) char sm[];
    uint32_t smb = (uint32_t)__cvta_generic_to_shared(sm);
    float* W2s = (float*)(sm + OFF_W2);

    int tid = threadIdx.x, lane = tid & 31, wid = tid >> 5;
    int is64 = g_is64;

    // Stage W1c (cols 128..191) as fp16, rows = output o, K-major, 144B rows
    for (int i = tid; i < HDIM * 16; i += THREADS) {
        int o = i >> 4, r = i & 15;
        float4 v = *(const float4*)(W1 + o * HDIM + 128 + r * 4);
        *(uint2*)(sm + OFF_W + o * ROWB + r * 8) = pack_h4(v);
    }
    for (int i = tid; i < HDIM; i += THREADS) W2s[i] = W2[i];
    __syncthreads();

    char* Ah  = sm + OFF_A + wid * AWARP;       // fp16 rows [16][144]
    char* F32 = Ah + 2304;                      // fp32 rows [16][272]
    uint32_t ah_u = smb + OFF_A + wid * AWARP;
    uint32_t w_u  = smb + OFF_W;
    int*   sSw = (int*)(sm + OFF_SS) + wid * 16;
    int*   sDw = (int*)(sm + OFF_SD) + wid * 16;
    float* ATw = (float*)(sm + OFF_AT) + wid * 16;

    int gw = blockIdx.x * NWARP + wid;
    for (int wt = gw; wt < nwt; wt += gridDim.x * NWARP) {
        int tbase = wt * 16;
        // ---- stage indices ----
        if (lane < 16) {
            int ge = tbase + lane;
            int s = 0, d = 0;
            if (ge < E) {
                s = (int)ldidx(ei, ge, is64);
                d = (int)ldidx(ei, E + ge, is64);
            }
            sSw[lane] = s; sDw[lane] = d;
        }
        __syncwarp();
        // ---- gather adj rows: fp16 copy for MMA + fp32 copy for output ----
        {
            int r = lane >> 1, h = lane & 1;
            int ge = tbase + r;
            int s = sSw[r], d = sDw[r];
            const float4* rowp =
                (const float4*)(adj + ((long long)s * NNODES + (d & (NNODES - 1))) * D);
            #pragma unroll
            for (int j = 0; j < 8; ++j) {
                float4 v = (ge < E) ? rowp[h * 8 + j]
                                    : make_float4(0.f, 0.f, 0.f, 0.f);
                *(uint2*)(Ah + r * ROWB + (h * 8 + j) * 8) = pack_h4(v);
                *(float4*)(F32 + r * F32RB + (h * 8 + j) * 16) = v;
            }
        }
        __syncwarp();

        int r0 = lane >> 2, r1 = r0 + 8;
        int s0 = sSw[r0], d0 = sDw[r0], s1 = sSw[r1], d1 = sDw[r1];
        const __half2* pd0 = (const __half2*)(g_PdH + d0 * HDIM);
        const __half2* ps0 = (const __half2*)(g_PsH + s0 * HDIM);
        const __half2* pd1 = (const __half2*)(g_PdH + d1 * HDIM);
        const __half2* ps1 = (const __half2*)(g_PsH + s1 * HDIM);

        // A fragments are nc-invariant: hoist (4 kk x 4 regs)
        uint32_t ahf[4][4];
        #pragma unroll
        for (int kk = 0; kk < 4; ++kk) {
            uint32_t aoff = (uint32_t)((lane & 15) * ROWB + kk * 32 + (lane >> 4) * 16);
            ldsm4(ahf[kk], ah_u + aoff);
        }

        float z0 = 0.0f, z1 = 0.0f;
        #pragma unroll
        for (int nc = 0; nc < 3; ++nc) {
            float acc[8][4] = {};
            int cb = nc * 64;
            #pragma unroll
            for (int kk = 0; kk < 4; ++kk) {
                #pragma unroll
                for (int fp = 0; fp < 4; ++fp) {
                    // B frags for col groups f=2fp, 2fp+1 in one ldsm4
                    uint32_t wa = w_u + (uint32_t)((cb + fp * 16 + (lane & 7) + ((lane >> 4) << 3)) * ROWB
                                                   + kk * 32 + ((lane >> 3) & 1) * 16);
                    uint32_t bh[4];
                    ldsm4(bh, wa);
                    mma_fp16(acc[2 * fp],     ahf[kk], bh);
                    mma_fp16(acc[2 * fp + 1], ahf[kk], bh + 2);
                }
            }
            // epilogue: x = acc + Pd[dst] + Ps[src] (fp16 P), z += gelu(x)*W2
            #pragma unroll
            for (int f = 0; f < 8; ++f) {
                int c0 = cb + f * 8 + 2 * (lane & 3);   // even
                int ch = c0 >> 1;
                float2 a0 = __half22float2(pd0[ch]);
                float2 b0 = __half22float2(ps0[ch]);
                float2 a1 = __half22float2(pd1[ch]);
                float2 b1 = __half22float2(ps1[ch]);
                float2 w2v = *(const float2*)(W2s + c0);
                z0 = fmaf(gelu_x(acc[f][0] + a0.x + b0.x), w2v.x, z0);
                z0 = fmaf(gelu_x(acc[f][1] + a0.y + b0.y), w2v.y, z0);
                z1 = fmaf(gelu_x(acc[f][2] + a1.x + b1.x), w2v.x, z1);
                z1 = fmaf(gelu_x(acc[f][3] + a1.y + b1.y), w2v.y, z1);
            }
        }
        // quad reduce (lanes sharing the same rows)
        z0 += __shfl_xor_sync(0xffffffffu, z0, 1);
        z0 += __shfl_xor_sync(0xffffffffu, z0, 2);
        z1 += __shfl_xor_sync(0xffffffffu, z1, 1);
        z1 += __shfl_xor_sync(0xffffffffu, z1, 2);

        if ((lane & 3) == 0) {
            int df0 = (s0 > d0 ? s0 - d0 : d0 - s0);
            int df1 = (s1 > d1 ? s1 - d1 : d1 - s1);
            float at0 = (tbase + r0 < E && df0 > 1) ? expf(z0) : 0.0f;
            float at1 = (tbase + r1 < E && df1 > 1) ? expf(z1) : 0.0f;
            ATw[r0] = at0; ATw[r1] = at1;
            if (at0 != 0.0f) atomicAdd(&g_denom[d0], at0);
            if (at1 != 0.0f) atomicAdd(&g_denom[d1], at1);
        }
        __syncwarp();

        // weighted accumulate from the exact fp32 rows: 2 edges/pass, red.v4
        #pragma unroll
        for (int ep = 0; ep < 8; ++ep) {
            int e = 2 * ep + (lane >> 4);
            float a = ATw[e];
            if (a != 0.0f) {
                int c4 = lane & 15;
                float4 v = *(const float4*)(F32 + e * F32RB + c4 * 16);
                red4(out + sDw[e] * D + c4 * 4, v.x * a, v.y * a, v.z * a, v.w * a);
            }
        }
        __syncwarp();
    }
}

__global__ void finalize_kernel(float* __restrict__ out) {
    int i = blockIdx.x * blockDim.x + threadIdx.x;   // 65536 threads, float4 each
    float dn = g_denom[i >> 4];
    float inv = 1.0f / (dn == 0.0f ? 1.0f : dn);
    float4 v = ((float4*)out)[i];
    v.x *= inv; v.y *= inv; v.z *= inv; v.w *= inv;
    ((float4*)out)[i] = v;
}

extern "C" void kernel_launch(void* const* d_in, const int* in_sizes, int n_in,
                              void* d_out, int out_size) {
    const float* nf  = (const float*)d_in[0];
    const float* adj = (const float*)d_in[1];
    const float* W1  = (const float*)d_in[2];
    const float* W2  = (const float*)d_in[3];
    const void*  ei  = d_in[4];
    int E = in_sizes[4] / 2;
    if (E > EMAX) E = EMAX;

    const int pre_smem = (64 * HDIM + 64 * 64) * sizeof(float);
    cudaFuncSetAttribute(precompute_kernel, cudaFuncAttributeMaxDynamicSharedMemorySize, pre_smem);
    cudaFuncSetAttribute(score_kernel, cudaFuncAttributeMaxDynamicSharedMemorySize, SMEM_TOTAL);

    precompute_kernel<<<(NTOT / 64) * 2, 256, pre_smem>>>(nf, W1, ei, (float*)d_out);

    int nwt = (E + 15) / 16;
    score_kernel<<<148, THREADS, SMEM_TOTAL>>>(adj, W1, W2, ei, (float*)d_out, E, nwt);

    finalize_kernel<<<256, 256>>>((float*)d_out);
}